// round 1
// baseline (speedup 1.0000x reference)
#include <cuda_runtime.h>
#include <cstdint>

#define Bq 16
#define Nq 2048
#define Cq 3
#define Kq 100
#define THREADS 256
#define PER (Nq / THREADS)   // 8 positions owned per thread
#define NWORD (Nq / 64)      // 32 bitmap words
#define NEGV (-1e9f)

// Map float to a key such that ascending-uint == DESCENDING-float order.
__device__ __forceinline__ unsigned fkey_desc(float f) {
    unsigned u = __float_as_uint(f);
    u = (u & 0x80000000u) ? ~u : (u | 0x80000000u);  // ascending order map
    return ~u;                                        // invert -> descending
}

__global__ void __launch_bounds__(THREADS)
roiheads_kernel(const float* __restrict__ logit,   // [B,N,3]
                const float* __restrict__ reg,     // [B,N,6]
                const float* __restrict__ prop,    // [B,N,2]
                const int*   __restrict__ ishape,  // scalar (int32 or float bits)
                float*       __restrict__ out)     // [B,2,K,3]
{
    __shared__ unsigned long long keys[Nq];
    __shared__ float slo[Nq], shi[Nq], ssc[Nq];
    __shared__ unsigned long long alive[NWORD];
    __shared__ int   wp[NWORD + 1];
    __shared__ int   sPivot;
    __shared__ float sPl, sPh;

    const int b   = blockIdx.x >> 1;
    const int c   = blockIdx.x & 1;   // fg class slot
    const int cls = c + 1;            // class index in logits/deltas
    const int tid = threadIdx.x;

    // image_shape: harness may pass int32(360) or float32(360.0)
    int ib = ishape[0];
    float img = (ib > 0 && ib < (1 << 24)) ? (float)ib : __int_as_float(ib);

    // ---------- Phase 1: softmax + decode + clip + mask, build sort keys ----------
    for (int j = tid; j < Nq; j += THREADS) {
        const float* lg = logit + ((size_t)b * Nq + j) * Cq;
        float l0 = lg[0], l1 = lg[1], l2 = lg[2];
        float m  = fmaxf(l0, fmaxf(l1, l2));
        float e0 = expf(l0 - m), e1 = expf(l1 - m), e2 = expf(l2 - m);
        float s  = ((cls == 1) ? e1 : e2) / (e0 + e1 + e2);

        const float* dd = reg + ((size_t)b * Nq + j) * (2 * Cq) + 2 * cls;
        float dx = dd[0];
        float dw = fminf(dd[1], 4.0f);

        const float* pp = prop + ((size_t)b * Nq + j) * 2;
        float p0 = pp[0], p1 = pp[1];
        float w   = p1 - p0;
        float ctr = p0 + 0.5f * w;
        float pc  = dx * w + ctr;
        float pw  = expf(dw) * w;
        float lo  = pc - 0.5f * pw;
        float hi  = pc + 0.5f * pw;
        lo = fminf(fmaxf(lo, 0.0f), img);
        hi = fminf(fmaxf(hi, 0.0f), img);

        bool  valid = ((hi - lo) >= 10.0f) && (s >= 0.05f);
        float ms    = valid ? s : NEGV;

        slo[j] = lo;  shi[j] = hi;  ssc[j] = ms;
        keys[j] = ((unsigned long long)fkey_desc(ms) << 32) | (unsigned)j;
    }
    __syncthreads();

    // ---------- Phase 2: bitonic sort ascending on composite key ----------
    // == stable sort by score desc, index asc (exactly argsort(-ms))
    for (int k = 2; k <= Nq; k <<= 1) {
        for (int j2 = k >> 1; j2 > 0; j2 >>= 1) {
            for (int i = tid; i < Nq; i += THREADS) {
                int ix = i ^ j2;
                if (ix > i) {
                    bool up = ((i & k) == 0);
                    unsigned long long a = keys[i], bb = keys[ix];
                    if ((a > bb) == up) { keys[i] = bb; keys[ix] = a; }
                }
            }
            __syncthreads();
        }
    }

    // ---------- Phase 3: init keep bitmap + cache owned entries ----------
    if (tid < NWORD) alive[tid] = 0ull;
    __syncthreads();

    int   myIdx[PER];
    float myLo[PER], myHi[PER];
    unsigned myAlive = 0;
    #pragma unroll
    for (int r = 0; r < PER; r++) {
        int p   = tid + r * THREADS;            // sorted position owned
        int idx = (int)(keys[p] & 0xffffffffu); // original index
        myIdx[r] = idx;
        myLo[r]  = slo[idx];
        myHi[r]  = shi[idx];
        if (ssc[idx] > 0.5f * NEGV) {           // keep0 = s > 0.5*NEG (valid only)
            myAlive |= (1u << r);
            atomicOr(&alive[p >> 6], 1ull << (p & 63));
        }
    }
    __syncthreads();

    // ---------- Phase 4: greedy NMS, pivot rounds ----------
    int pivot = -1;
    for (;;) {
        if (tid == 0) {
            int p  = pivot + 1;
            int w  = p >> 6;
            int np = -1;
            unsigned long long word =
                (w < NWORD) ? (alive[w] & (~0ull << (p & 63))) : 0ull;
            while (w < NWORD) {
                if (word) { np = (w << 6) + __ffsll(word) - 1; break; }
                ++w;
                if (w < NWORD) word = alive[w];
            }
            sPivot = np;
            if (np >= 0) {
                int idx = (int)(keys[np] & 0xffffffffu);
                sPl = slo[idx];
                sPh = shi[idx];
            }
        }
        __syncthreads();
        pivot = sPivot;
        if (pivot < 0) break;
        float pl = sPl, ph = sPh;
        float pwid = ph - pl;

        // Suppress my alive positions strictly after the pivot
        unsigned am = myAlive;
        while (am) {
            int r = __ffs(am) - 1;
            am &= am - 1;
            int p = tid + r * THREADS;
            if (p <= pivot) continue;
            float lo = myLo[r], hi = myHi[r];
            float inter = fminf(ph, hi) - fmaxf(pl, lo);
            if (inter > 0.0f) {
                float uni = pwid + (hi - lo) - inter;
                float iou = inter / fmaxf(uni, 1e-8f);  // IEEE div == reference
                if (iou > 0.5f) {
                    myAlive &= ~(1u << r);
                    atomicAnd(&alive[p >> 6], ~(1ull << (p & 63)));
                }
            }
        }
        __syncthreads();
    }

    // ---------- Phase 5: ranks + emit top-K with NEG padding ----------
    if (tid == 0) {
        int acc = 0;
        #pragma unroll
        for (int w = 0; w < NWORD; w++) { wp[w] = acc; acc += __popcll(alive[w]); }
        wp[NWORD] = acc;
    }
    __syncthreads();
    const int T = wp[NWORD];                    // total kept
    float* o = out + ((size_t)(b * 2 + c)) * Kq * 3;

    #pragma unroll
    for (int r = 0; r < PER; r++) {
        int p = tid + r * THREADS;
        int w = p >> 6;
        unsigned long long lowmask = (1ull << (p & 63)) - 1ull;
        int  kr   = wp[w] + __popcll(alive[w] & lowmask); // kept rank (exclusive)
        bool kept = (alive[w] >> (p & 63)) & 1ull;
        if (kept) {
            if (kr < Kq) {
                o[kr * 3 + 0] = myLo[r];
                o[kr * 3 + 1] = myHi[r];
                o[kr * 3 + 2] = ssc[myIdx[r]];
            }
        } else {
            int nr = p - kr;                    // non-kept rank (lowest index first)
            if (T < Kq && nr < Kq - T) {
                int slot = T + nr;
                o[slot * 3 + 0] = myLo[r];
                o[slot * 3 + 1] = myHi[r];
                o[slot * 3 + 2] = NEGV;
            }
        }
    }
}

extern "C" void kernel_launch(void* const* d_in, const int* in_sizes, int n_in,
                              void* d_out, int out_size)
{
    const float* logit  = (const float*)d_in[0];   // [16,2048,3]
    const float* reg    = (const float*)d_in[1];   // [16,2048,6]
    const float* prop   = (const float*)d_in[2];   // [16,2048,2]
    const int*   ishape = (const int*)d_in[3];     // scalar
    float* out = (float*)d_out;                    // [16,2,100,3]

    roiheads_kernel<<<Bq * (Cq - 1), THREADS>>>(logit, reg, prop, ishape, out);
}

// round 2
// speedup vs baseline: 1.0760x; 1.0760x over previous
#include <cuda_runtime.h>
#include <cstdint>

#define Bq 16
#define Nq 2048
#define Cq 3
#define Kq 100
#define THREADS 256
#define PER (Nq / THREADS)   // 8 contiguous positions owned per thread
#define NWORD (Nq / 64)      // 32 bitmap words
#define NTILE (Nq / 64)      // 32 tiles of 64 sorted positions
#define NEGV (-1e9f)

typedef unsigned long long u64;

// float -> key: ascending-uint == DESCENDING-float order.
__device__ __forceinline__ unsigned fkey_desc(float f) {
    unsigned u = __float_as_uint(f);
    u = (u & 0x80000000u) ? ~u : (u | 0x80000000u);
    return ~u;
}
// lossless inverse
__device__ __forceinline__ float key_to_score(unsigned k) {
    unsigned u = ~k;
    u = (u & 0x80000000u) ? (u & 0x7fffffffu) : ~u;
    return __uint_as_float(u);
}

__global__ void __launch_bounds__(THREADS)
roiheads_kernel(const float* __restrict__ logit,   // [B,N,3]
                const float* __restrict__ reg,     // [B,N,6]
                const float* __restrict__ prop,    // [B,N,2]
                const int*   __restrict__ ishape,  // scalar
                float*       __restrict__ out)     // [B,2,K,3]
{
    __shared__ u64    keys[Nq];          // 16 KB  (scoreKey<<32 | idx)
    __shared__ float2 lohi[Nq];          // 16 KB  idx-indexed clipped boxes
    __shared__ float  tileLo[64], tileHi[64];
    __shared__ u64    sup[64];
    __shared__ u64    alive[NWORD];
    __shared__ u64    sKept;
    __shared__ int    sSkip;
    __shared__ int    wp[NWORD + 1];

    const int b   = blockIdx.x >> 1;
    const int c   = blockIdx.x & 1;
    const int cls = c + 1;
    const int tid = threadIdx.x;
    const int base = tid * PER;          // first owned sorted position

    int ib = ishape[0];
    float img = (ib > 0 && ib < (1 << 24)) ? (float)ib : __int_as_float(ib);

    if (tid < NWORD) alive[tid] = 0ull;

    // ---------- Phase 1: softmax + decode + clip + mask -> keys ----------
    for (int j = tid; j < Nq; j += THREADS) {
        const float* lg = logit + ((size_t)b * Nq + j) * Cq;
        float l0 = lg[0], l1 = lg[1], l2 = lg[2];
        float m  = fmaxf(l0, fmaxf(l1, l2));
        float e0 = expf(l0 - m), e1 = expf(l1 - m), e2 = expf(l2 - m);
        float s  = ((cls == 1) ? e1 : e2) / (e0 + e1 + e2);

        const float* dd = reg + ((size_t)b * Nq + j) * (2 * Cq) + 2 * cls;
        float dx = dd[0];
        float dw = fminf(dd[1], 4.0f);

        const float* pp = prop + ((size_t)b * Nq + j) * 2;
        float p0 = pp[0], p1 = pp[1];
        float w   = p1 - p0;
        float ctr = p0 + 0.5f * w;
        float pc  = dx * w + ctr;
        float pw  = expf(dw) * w;
        float lo  = fminf(fmaxf(pc - 0.5f * pw, 0.0f), img);
        float hi  = fminf(fmaxf(pc + 0.5f * pw, 0.0f), img);

        bool  valid = ((hi - lo) >= 10.0f) && (s >= 0.05f);
        float ms    = valid ? s : NEGV;

        lohi[j] = make_float2(lo, hi);
        keys[j] = ((u64)fkey_desc(ms) << 32) | (unsigned)j;
    }
    __syncthreads();

    // ---------- Phase 2: hybrid bitonic sort (ascending composite key) ----------
    // == stable argsort(-ms): score desc, index asc.
    for (int k = 2; k <= Nq; k <<= 1) {
        // barriered passes for stride >= 8
        for (int j2 = k >> 1; j2 >= PER; j2 >>= 1) {
            #pragma unroll
            for (int rr = 0; rr < PER; rr++) {
                int i  = tid + rr * THREADS;
                int ix = i ^ j2;
                if (ix > i) {
                    bool up = ((i & k) == 0);
                    u64 a = keys[i], bb = keys[ix];
                    if ((a > bb) == up) { keys[i] = bb; keys[ix] = a; }
                }
            }
            __syncthreads();
        }
        // register-local passes: strides 4,2,1 within the owned 8
        {
            u64 v[PER];
            #pragma unroll
            for (int r = 0; r < PER; r++) v[r] = keys[base + r];
            #pragma unroll
            for (int j2 = 4; j2 >= 1; j2 >>= 1) {
                if (j2 < k) {
                    #pragma unroll
                    for (int r = 0; r < PER; r++) {
                        int rx = r ^ j2;
                        if (rx > r) {
                            bool up = (((base + r) & k) == 0);
                            u64 a = v[r], bb = v[rx];
                            if ((a > bb) == up) { v[r] = bb; v[rx] = a; }
                        }
                    }
                }
            }
            #pragma unroll
            for (int r = 0; r < PER; r++) keys[base + r] = v[r];
        }
        __syncthreads();
    }

    // ---------- Phase 3: gather owned boxes, build alive bitmap ----------
    float myLo[PER], myHi[PER];
    unsigned myAlive = 0;
    #pragma unroll
    for (int r = 0; r < PER; r++) {
        u64 key = keys[base + r];
        int idx = (int)(key & 0xffffffffu);
        float2 lh = lohi[idx];
        myLo[r] = lh.x;
        myHi[r] = lh.y;
        if (key_to_score((unsigned)(key >> 32)) > 0.5f * NEGV)
            myAlive |= (1u << r);
    }
    if (myAlive)
        atomicOr(&alive[tid >> 3], (u64)myAlive << ((tid & 7) * PER));
    __syncthreads();

    // ---------- Phase 4: tile-serialized exact greedy NMS ----------
    for (int t = 0; t < NTILE; t++) {
        // A: publish tile boxes, zero sup, check skip
        if (tid == 0) sSkip = (alive[t] == 0ull);
        if ((tid >> 3) == t) {
            int o = (tid & 7) * PER;
            #pragma unroll
            for (int r = 0; r < PER; r++) { tileLo[o + r] = myLo[r]; tileHi[o + r] = myHi[r]; }
        }
        if (tid < 64) sup[tid] = 0ull;
        __syncthreads();
        if (sSkip) continue;

        // B: pairwise suppression masks (upper triangle), 16 pairs/thread
        {
            int i = tid >> 2;
            int q = (tid & 3) * 16;
            float li = tileLo[i], hii = tileHi[i];
            float wi = hii - li;
            u64 bits = 0;
            #pragma unroll
            for (int jj = 0; jj < 16; jj++) {
                int j = q + jj;
                if (j > i) {
                    float lj = tileLo[j], hj = tileHi[j];
                    float inter = fminf(hii, hj) - fmaxf(li, lj);
                    if (inter > 0.0f) {
                        float uni = wi + (hj - lj) - inter;
                        float iou = inter / fmaxf(uni, 1e-8f);
                        if (iou > 0.5f) bits |= (1ull << j);
                    }
                }
            }
            if (bits) atomicOr(&sup[i], bits);
        }
        __syncthreads();

        // C: serial intra-tile greedy (sup[i] only holds bits > i)
        if (tid == 0) {
            u64 aliveT = alive[t];
            u64 keptT  = 0;
            int pos = -1;
            while (true) {
                u64 rest = (pos >= 63) ? 0ull : (aliveT & (~0ull << (pos + 1)));
                if (!rest) break;
                pos = __ffsll(rest) - 1;
                keptT |= (1ull << pos);
                aliveT &= ~sup[pos];
            }
            alive[t] = keptT;
            sKept = keptT;
        }
        __syncthreads();

        // D: kept boxes of this tile suppress all later alive positions
        u64 keptT = sKept;
        if (keptT && tid >= (t + 1) * 8) {
            unsigned am = myAlive, killed = 0;
            while (am) {
                int r = __ffs(am) - 1;
                am &= am - 1;
                float lo = myLo[r], hi = myHi[r];
                float wb = hi - lo;
                u64 kk = keptT;
                while (kk) {
                    int s = __ffsll(kk) - 1;
                    kk &= kk - 1;
                    float pl = tileLo[s], ph = tileHi[s];
                    float inter = fminf(ph, hi) - fmaxf(pl, lo);
                    if (inter > 0.0f) {
                        float uni = (ph - pl) + wb - inter;
                        float iou = inter / fmaxf(uni, 1e-8f);
                        if (iou > 0.5f) { killed |= (1u << r); break; }
                    }
                }
            }
            if (killed) {
                myAlive &= ~killed;
                atomicAnd(&alive[tid >> 3], ~((u64)killed << ((tid & 7) * PER)));
            }
        }
        __syncthreads();
    }

    // ---------- Phase 5: ranks + emit top-K with NEG padding ----------
    if (tid == 0) {
        int acc = 0;
        #pragma unroll
        for (int w = 0; w < NWORD; w++) { wp[w] = acc; acc += __popcll(alive[w]); }
        wp[NWORD] = acc;
    }
    __syncthreads();
    const int T = wp[NWORD];
    float* o = out + ((size_t)(b * 2 + c)) * Kq * 3;

    const u64 aw = alive[tid >> 3];
    #pragma unroll
    for (int r = 0; r < PER; r++) {
        int p = base + r;
        int bit = p & 63;
        u64 lowmask = (bit == 0) ? 0ull : ((1ull << bit) - 1ull);
        int  kr   = wp[p >> 6] + __popcll(aw & lowmask);
        bool kept = (aw >> bit) & 1ull;
        if (kept) {
            if (kr < Kq) {
                o[kr * 3 + 0] = myLo[r];
                o[kr * 3 + 1] = myHi[r];
                o[kr * 3 + 2] = key_to_score((unsigned)(keys[p] >> 32));
            }
        } else {
            int nr = p - kr;                       // non-kept rank (lowest pos first)
            if (T < Kq && nr < Kq - T) {
                int slot = T + nr;
                o[slot * 3 + 0] = myLo[r];
                o[slot * 3 + 1] = myHi[r];
                o[slot * 3 + 2] = NEGV;
            }
        }
    }
}

extern "C" void kernel_launch(void* const* d_in, const int* in_sizes, int n_in,
                              void* d_out, int out_size)
{
    const float* logit  = (const float*)d_in[0];   // [16,2048,3]
    const float* reg    = (const float*)d_in[1];   // [16,2048,6]
    const float* prop   = (const float*)d_in[2];   // [16,2048,2]
    const int*   ishape = (const int*)d_in[3];     // scalar
    float* out = (float*)d_out;                    // [16,2,100,3]

    roiheads_kernel<<<Bq * (Cq - 1), THREADS>>>(logit, reg, prop, ishape, out);
}

// round 3
// speedup vs baseline: 1.4364x; 1.3350x over previous
#include <cuda_runtime.h>
#include <cstdint>

#define Bq 16
#define Nq 2048
#define Cq 3
#define Kq 100
#define THREADS 512
#define PER (Nq / THREADS)   // 4 contiguous sorted positions per thread
#define NWORD (Nq / 64)      // 32 bitmap words
#define NTILE (Nq / 64)      // 32 tiles of 64 sorted positions
#define NEGV (-1e9f)

typedef unsigned long long u64;

// float -> key: ascending-uint == DESCENDING-float order.
__device__ __forceinline__ unsigned fkey_desc(float f) {
    unsigned u = __float_as_uint(f);
    u = (u & 0x80000000u) ? ~u : (u | 0x80000000u);
    return ~u;
}
// lossless inverse
__device__ __forceinline__ float key_to_score(unsigned k) {
    unsigned u = ~k;
    u = (u & 0x80000000u) ? (u & 0x7fffffffu) : ~u;
    return __uint_as_float(u);
}

__global__ void __launch_bounds__(THREADS)
roiheads_kernel(const float* __restrict__ logit,   // [B,N,3]
                const float* __restrict__ reg,     // [B,N,6]
                const float* __restrict__ prop,    // [B,N,2]
                const int*   __restrict__ ishape,  // scalar
                float*       __restrict__ out)     // [B,2,K,3]
{
    __shared__ u64    keys[Nq];          // (scoreKey<<32 | idx), sorted
    __shared__ float2 lohi[Nq];          // idx-indexed clipped boxes
    __shared__ float  tileLo[64], tileHi[64];
    __shared__ float  keptLo[64], keptHi[64];   // compacted kept of current tile
    __shared__ u64    sup[64];
    __shared__ u64    alive[NWORD];
    __shared__ int    sSkipB[2];         // double-buffered skip flag
    __shared__ int    sNk, sStop, sStopT, sKeptTotal;
    __shared__ int    wp[NWORD + 1];

    const int b   = blockIdx.x >> 1;
    const int c   = blockIdx.x & 1;
    const int cls = c + 1;
    const int tid = threadIdx.x;
    const int base = tid * PER;          // first owned sorted position

    int ib = ishape[0];
    float img = (ib > 0 && ib < (1 << 24)) ? (float)ib : __int_as_float(ib);

    if (tid < NWORD) alive[tid] = 0ull;
    if (tid == 0) { sKeptTotal = 0; sStop = 0; sStopT = NTILE - 1; }

    // ---------- Phase 1: softmax + decode + clip + mask -> keys ----------
    #pragma unroll
    for (int it = 0; it < PER; it++) {
        int j = tid + it * THREADS;
        const float* lg = logit + ((size_t)b * Nq + j) * Cq;
        float l0 = lg[0], l1 = lg[1], l2 = lg[2];
        float m  = fmaxf(l0, fmaxf(l1, l2));
        float e0 = expf(l0 - m), e1 = expf(l1 - m), e2 = expf(l2 - m);
        float s  = ((cls == 1) ? e1 : e2) / (e0 + e1 + e2);

        const float* dd = reg + ((size_t)b * Nq + j) * (2 * Cq) + 2 * cls;
        float dx = dd[0];
        float dw = fminf(dd[1], 4.0f);

        const float* pp = prop + ((size_t)b * Nq + j) * 2;
        float p0 = pp[0], p1 = pp[1];
        float w   = p1 - p0;
        float ctr = p0 + 0.5f * w;
        float pc  = dx * w + ctr;
        float pw  = expf(dw) * w;
        float lo  = fminf(fmaxf(pc - 0.5f * pw, 0.0f), img);
        float hi  = fminf(fmaxf(pc + 0.5f * pw, 0.0f), img);

        bool  valid = ((hi - lo) >= 10.0f) && (s >= 0.05f);
        float ms    = valid ? s : NEGV;

        lohi[j] = make_float2(lo, hi);
        keys[j] = ((u64)fkey_desc(ms) << 32) | (unsigned)j;
    }
    __syncthreads();

    // ---------- Phase 2: hybrid bitonic sort (ascending composite key) ----------
    // == stable argsort(-ms): score desc, index asc.
    for (int k = 2; k <= Nq; k <<= 1) {
        for (int j2 = k >> 1; j2 >= PER; j2 >>= 1) {
            #pragma unroll
            for (int rr = 0; rr < PER; rr++) {
                int i  = tid + rr * THREADS;
                int ix = i ^ j2;
                if (ix > i) {
                    bool up = ((i & k) == 0);
                    u64 a = keys[i], bb = keys[ix];
                    if ((a > bb) == up) { keys[i] = bb; keys[ix] = a; }
                }
            }
            __syncthreads();
        }
        // register-local strides 2,1 within the owned 4
        {
            u64 v[PER];
            #pragma unroll
            for (int r = 0; r < PER; r++) v[r] = keys[base + r];
            #pragma unroll
            for (int j2 = 2; j2 >= 1; j2 >>= 1) {
                if (j2 < k) {
                    #pragma unroll
                    for (int r = 0; r < PER; r++) {
                        int rx = r ^ j2;
                        if (rx > r) {
                            bool up = (((base + r) & k) == 0);
                            u64 a = v[r], bb = v[rx];
                            if ((a > bb) == up) { v[r] = bb; v[rx] = a; }
                        }
                    }
                }
            }
            #pragma unroll
            for (int r = 0; r < PER; r++) keys[base + r] = v[r];
        }
        __syncthreads();
    }

    // ---------- Phase 3: gather owned boxes, build alive bitmap ----------
    float myLo[PER], myHi[PER];
    unsigned myAlive = 0;
    #pragma unroll
    for (int r = 0; r < PER; r++) {
        u64 key = keys[base + r];
        int idx = (int)(key & 0xffffffffu);
        float2 lh = lohi[idx];
        myLo[r] = lh.x;
        myHi[r] = lh.y;
        if (key_to_score((unsigned)(key >> 32)) > 0.5f * NEGV)
            myAlive |= (1u << r);
    }
    if (myAlive)
        atomicOr(&alive[tid >> 4], (u64)myAlive << ((tid & 15) * PER));
    __syncthreads();

    // ---------- Phase 4: tile NMS with early stop at K kept ----------
    for (int t = 0; t < NTILE; t++) {
        // A: publish tile boxes, zero sup, skip flag (double-buffered)
        if (tid == 0) sSkipB[t & 1] = (alive[t] == 0ull);
        if ((tid >> 4) == t) {
            int o = (tid & 15) * PER;
            #pragma unroll
            for (int r = 0; r < PER; r++) { tileLo[o + r] = myLo[r]; tileHi[o + r] = myHi[r]; }
        }
        if (tid < 64) sup[tid] = 0ull;
        __syncthreads();
        if (sSkipB[t & 1]) continue;

        // B: pairwise suppression bits (upper triangle), 8 pairs/thread
        {
            int i = tid >> 3;
            int q = (tid & 7) * 8;
            float li = tileLo[i], hii = tileHi[i];
            float wi = hii - li;
            u64 bits = 0;
            #pragma unroll
            for (int jj = 0; jj < 8; jj++) {
                int j = q + jj;
                if (j > i) {
                    float lj = tileLo[j], hj = tileHi[j];
                    float inter = fminf(hii, hj) - fmaxf(li, lj);
                    if (inter > 0.0f) {
                        float uni = wi + (hj - lj) - inter;
                        if (inter / fmaxf(uni, 1e-8f) > 0.5f) bits |= (1ull << j);
                    }
                }
            }
            if (bits) atomicOr(&sup[i], bits);
        }
        __syncthreads();

        // C: serial intra-tile greedy + compact kept boxes
        if (tid == 0) {
            u64 aliveT = alive[t];
            u64 keptT  = 0;
            int pos = -1, nk = 0;
            while (true) {
                u64 rest = (pos >= 63) ? 0ull : (aliveT & (~0ull << (pos + 1)));
                if (!rest) break;
                pos = __ffsll(rest) - 1;
                keptT |= (1ull << pos);
                aliveT &= ~sup[pos];
                keptLo[nk] = tileLo[pos];
                keptHi[nk] = tileHi[pos];
                nk++;
            }
            alive[t] = keptT;
            sNk = nk;
            int kt = sKeptTotal + nk;
            sKeptTotal = kt;
            if (kt >= Kq) { sStop = 1; sStopT = t; }
        }
        __syncthreads();
        if (sStop) break;   // first K kept found; later tiles irrelevant

        // D: this tile's kept suppress later alive positions (counted loop)
        const int nk = sNk;
        if (tid >= (t + 1) * 16 && myAlive) {
            unsigned killed = 0;
            #pragma unroll
            for (int r = 0; r < PER; r++) {
                if (myAlive & (1u << r)) {
                    float lo = myLo[r], hi = myHi[r];
                    float wb = hi - lo;
                    for (int s = 0; s < nk; s++) {
                        float pl = keptLo[s], ph = keptHi[s];
                        float inter = fminf(ph, hi) - fmaxf(pl, lo);
                        if (inter > 0.0f) {
                            float uni = (ph - pl) + wb - inter;
                            if (inter / fmaxf(uni, 1e-8f) > 0.5f) { killed |= (1u << r); break; }
                        }
                    }
                }
            }
            if (killed) {
                myAlive &= ~killed;
                atomicAnd(&alive[tid >> 4], ~((u64)killed << ((tid & 15) * PER)));
            }
        }
        __syncthreads();
    }

    // Unresolved tiles past the stop point contribute nothing
    if (tid < NWORD && tid > sStopT) alive[tid] = 0ull;
    __syncthreads();

    // ---------- Phase 5: ranks + emit top-K with NEG padding ----------
    if (tid == 0) {
        int acc = 0;
        #pragma unroll
        for (int w = 0; w < NWORD; w++) { wp[w] = acc; acc += __popcll(alive[w]); }
        wp[NWORD] = acc;
    }
    __syncthreads();
    const int T = wp[NWORD];
    float* o = out + ((size_t)(b * 2 + c)) * Kq * 3;

    const u64 aw = alive[tid >> 4];
    #pragma unroll
    for (int r = 0; r < PER; r++) {
        int p = base + r;
        int bit = p & 63;
        u64 lowmask = (bit == 0) ? 0ull : ((1ull << bit) - 1ull);
        int  kr   = wp[p >> 6] + __popcll(aw & lowmask);
        bool kept = (aw >> bit) & 1ull;
        if (kept) {
            if (kr < Kq) {
                o[kr * 3 + 0] = myLo[r];
                o[kr * 3 + 1] = myHi[r];
                o[kr * 3 + 2] = key_to_score((unsigned)(keys[p] >> 32));
            }
        } else {
            int nr = p - kr;                       // non-kept rank (lowest pos first)
            if (T < Kq && nr < Kq - T) {
                int slot = T + nr;
                o[slot * 3 + 0] = myLo[r];
                o[slot * 3 + 1] = myHi[r];
                o[slot * 3 + 2] = NEGV;
            }
        }
    }
}

extern "C" void kernel_launch(void* const* d_in, const int* in_sizes, int n_in,
                              void* d_out, int out_size)
{
    const float* logit  = (const float*)d_in[0];   // [16,2048,3]
    const float* reg    = (const float*)d_in[1];   // [16,2048,6]
    const float* prop   = (const float*)d_in[2];   // [16,2048,2]
    const int*   ishape = (const int*)d_in[3];     // scalar
    float* out = (float*)d_out;                    // [16,2,100,3]

    roiheads_kernel<<<Bq * (Cq - 1), THREADS>>>(logit, reg, prop, ishape, out);
}

// round 4
// speedup vs baseline: 1.8856x; 1.3127x over previous
#include <cuda_runtime.h>
#include <cstdint>

#define Bq 16
#define Nq 2048
#define Cq 3
#define Kq 100
#define THREADS 512
#define PER (Nq / THREADS)   // 4 contiguous sorted positions per thread
#define NWORD (Nq / 64)      // 32 bitmap words
#define NTILE (Nq / 64)      // 32 tiles of 64 sorted positions
#define NEGV (-1e9f)

typedef unsigned long long u64;

// float -> key: ascending-uint == DESCENDING-float order.
__device__ __forceinline__ unsigned fkey_desc(float f) {
    unsigned u = __float_as_uint(f);
    u = (u & 0x80000000u) ? ~u : (u | 0x80000000u);
    return ~u;
}
// lossless inverse
__device__ __forceinline__ float key_to_score(unsigned k) {
    unsigned u = ~k;
    u = (u & 0x80000000u) ? (u & 0x7fffffffu) : ~u;
    return __uint_as_float(u);
}

__global__ void __launch_bounds__(THREADS)
roiheads_kernel(const float* __restrict__ logit,   // [B,N,3]
                const float* __restrict__ reg,     // [B,N,6]
                const float* __restrict__ prop,    // [B,N,2]
                const int*   __restrict__ ishape,  // scalar
                float*       __restrict__ out)     // [B,2,K,3]
{
    __shared__ u64    keys[Nq];          // scratch for high-stride sort passes only
    __shared__ float2 lohi[Nq];          // idx-indexed clipped boxes
    __shared__ float  tileLo[64], tileHi[64];
    __shared__ float  keptLo[64], keptHi[64];
    __shared__ u64    alive[NWORD];
    __shared__ int    sNk, sStop, sStopT, sKeptTotal;
    __shared__ int    wp[NWORD + 1];

    const int b   = blockIdx.x >> 1;
    const int c   = blockIdx.x & 1;
    const int cls = c + 1;
    const int tid = threadIdx.x;
    const int lane = tid & 31;
    const int base = tid * PER;          // first owned sorted position

    int ib = ishape[0];
    float img = (ib > 0 && ib < (1 << 24)) ? (float)ib : __int_as_float(ib);

    if (tid < NWORD) alive[tid] = 0ull;
    if (tid == 0) { sKeptTotal = 0; sStop = 0; sStopT = NTILE - 1; }

    // ---------- Phase 1: softmax + decode + clip + mask -> keys in regs ----------
    u64 v[PER];
    {
        // vectorized loads: 4 consecutive items per thread
        const float4* lgv = (const float4*)(logit + ((size_t)b * Nq + base) * Cq);
        float4 L0 = lgv[0], L1 = lgv[1], L2 = lgv[2];          // 12 floats
        const float4* ppv = (const float4*)(prop + ((size_t)b * Nq + base) * 2);
        float4 P0 = ppv[0], P1 = ppv[1];                        // 8 floats
        float lg[12] = {L0.x,L0.y,L0.z,L0.w,L1.x,L1.y,L1.z,L1.w,L2.x,L2.y,L2.z,L2.w};
        float pr[8]  = {P0.x,P0.y,P0.z,P0.w,P1.x,P1.y,P1.z,P1.w};

        #pragma unroll
        for (int r = 0; r < PER; r++) {
            int j = base + r;
            float l0 = lg[r*3+0], l1 = lg[r*3+1], l2 = lg[r*3+2];
            float m  = fmaxf(l0, fmaxf(l1, l2));
            float e0 = expf(l0 - m), e1 = expf(l1 - m), e2 = expf(l2 - m);
            float s  = ((cls == 1) ? e1 : e2) / (e0 + e1 + e2);

            const float2 dd = *(const float2*)(reg + ((size_t)b * Nq + j) * (2 * Cq) + 2 * cls);
            float dx = dd.x;
            float dw = fminf(dd.y, 4.0f);

            float p0 = pr[r*2+0], p1 = pr[r*2+1];
            float w   = p1 - p0;
            float ctr = p0 + 0.5f * w;
            float pc  = dx * w + ctr;
            float pw  = expf(dw) * w;
            float lo  = fminf(fmaxf(pc - 0.5f * pw, 0.0f), img);
            float hi  = fminf(fmaxf(pc + 0.5f * pw, 0.0f), img);

            bool  valid = ((hi - lo) >= 10.0f) && (s >= 0.05f);
            float ms    = valid ? s : NEGV;

            lohi[j] = make_float2(lo, hi);
            v[r] = ((u64)fkey_desc(ms) << 32) | (unsigned)j;
        }
    }

    // ---------- Phase 2: bitonic sort; smem only for strides >= 128 ----------
    for (int k = 2; k <= Nq; k <<= 1) {
        int j2 = k >> 1;
        if (j2 >= 128) {
            #pragma unroll
            for (int r = 0; r < PER; r++) keys[base + r] = v[r];
            __syncthreads();
            for (; j2 >= 128; j2 >>= 1) {
                #pragma unroll
                for (int rr = 0; rr < PER; rr++) {
                    int i  = tid + rr * THREADS;
                    int ix = i ^ j2;
                    if (ix > i) {
                        bool up = ((i & k) == 0);
                        u64 a = keys[i], bb = keys[ix];
                        if ((a > bb) == up) { keys[i] = bb; keys[ix] = a; }
                    }
                }
                __syncthreads();
            }
            #pragma unroll
            for (int r = 0; r < PER; r++) v[r] = keys[base + r];
        }
        // warp-local strides 64..4 via shuffle (partner within same warp)
        for (; j2 >= 4; j2 >>= 1) {
            int ld = j2 >> 2;   // lane delta
            #pragma unroll
            for (int r = 0; r < PER; r++) {
                u64 other = __shfl_xor_sync(0xffffffffu, v[r], ld);
                int i = base + r;
                bool up    = ((i & k)  == 0);
                bool lower = ((i & j2) == 0);
                bool tmin  = (up == lower);
                u64 mn = (v[r] < other) ? v[r] : other;
                u64 mx = (v[r] < other) ? other : v[r];
                v[r] = tmin ? mn : mx;
            }
        }
        // register-local strides 2,1
        #pragma unroll
        for (int j2r = 2; j2r >= 1; j2r >>= 1) {
            if (j2r < k) {
                #pragma unroll
                for (int r = 0; r < PER; r++) {
                    int rx = r ^ j2r;
                    if (rx > r) {
                        bool up = (((base + r) & k) == 0);
                        u64 a = v[r], bb = v[rx];
                        if ((a > bb) == up) { v[r] = bb; v[rx] = a; }
                    }
                }
            }
        }
    }

    // ---------- Phase 3: gather owned boxes, build alive bitmap ----------
    float myLo[PER], myHi[PER];
    unsigned myAlive = 0;
    #pragma unroll
    for (int r = 0; r < PER; r++) {
        int idx = (int)(v[r] & 0xffffffffu);
        float2 lh = lohi[idx];
        myLo[r] = lh.x;
        myHi[r] = lh.y;
        if (key_to_score((unsigned)(v[r] >> 32)) > 0.5f * NEGV)
            myAlive |= (1u << r);
    }
    if (myAlive)
        atomicOr(&alive[tid >> 4], (u64)myAlive << ((tid & 15) * PER));
    __syncthreads();

    // ---------- Phase 4: tile NMS — warp-ballot greedy + early stop ----------
    for (int t = 0; t < NTILE; t++) {
        u64 at0 = alive[t];          // safe: previous iter ended with barrier
        if (at0 == 0ull) continue;   // uniform branch, no writes -> no barrier needed

        // A: owners publish tile boxes
        if ((tid >> 4) == t) {
            int o = (tid & 15) * PER;
            #pragma unroll
            for (int r = 0; r < PER; r++) { tileLo[o + r] = myLo[r]; tileHi[o + r] = myHi[r]; }
        }
        __syncthreads();

        // C': warp 0 greedy over the tile (2 boxes per lane)
        if (tid < 32) {
            float lo0 = tileLo[lane],      hi0 = tileHi[lane];
            float lo1 = tileLo[lane + 32], hi1 = tileHi[lane + 32];
            u64 rest = at0;
            u64 kept = 0;
            int nk = 0;
            while (rest) {
                int pos = __ffsll((long long)rest) - 1;
                kept |= (1ull << pos);
                float candL = (pos & 32) ? lo1 : lo0;
                float candH = (pos & 32) ? hi1 : hi0;
                float pl = __shfl_sync(0xffffffffu, candL, pos & 31);
                float ph = __shfl_sync(0xffffffffu, candH, pos & 31);
                float pw = ph - pl;
                bool k0 = false, k1 = false;
                {
                    float inter = fminf(ph, hi0) - fmaxf(pl, lo0);
                    if (inter > 0.0f) {
                        float uni = pw + (hi0 - lo0) - inter;
                        k0 = inter / fmaxf(uni, 1e-8f) > 0.5f;
                    }
                    inter = fminf(ph, hi1) - fmaxf(pl, lo1);
                    if (inter > 0.0f) {
                        float uni = pw + (hi1 - lo1) - inter;
                        k1 = inter / fmaxf(uni, 1e-8f) > 0.5f;
                    }
                }
                unsigned b0 = __ballot_sync(0xffffffffu, k0);
                unsigned b1 = __ballot_sync(0xffffffffu, k1);
                u64 kill = ((u64)b0) | (((u64)b1) << 32);
                rest &= ~kill;
                rest = (pos < 63) ? (rest & (~0ull << (pos + 1))) : 0ull;
                if (lane == 0) { keptLo[nk] = pl; keptHi[nk] = ph; }
                nk++;
            }
            if (lane == 0) {
                alive[t] = kept;
                sNk = nk;
                int kt = sKeptTotal + nk;
                sKeptTotal = kt;
                if (kt >= Kq) { sStop = 1; sStopT = t; }
            }
        }
        __syncthreads();
        if (sStop) break;            // first K kept found; later tiles irrelevant

        // D: this tile's kept suppress later alive positions
        const int nk = sNk;
        if (tid >= (t + 1) * 16 && myAlive) {
            unsigned killed = 0;
            #pragma unroll
            for (int r = 0; r < PER; r++) {
                if (myAlive & (1u << r)) {
                    float lo = myLo[r], hi = myHi[r];
                    float wb = hi - lo;
                    for (int s = 0; s < nk; s++) {
                        float pl = keptLo[s], ph = keptHi[s];
                        float inter = fminf(ph, hi) - fmaxf(pl, lo);
                        if (inter > 0.0f) {
                            float uni = (ph - pl) + wb - inter;
                            if (inter / fmaxf(uni, 1e-8f) > 0.5f) { killed |= (1u << r); break; }
                        }
                    }
                }
            }
            if (killed) {
                myAlive &= ~killed;
                atomicAnd(&alive[tid >> 4], ~((u64)killed << ((tid & 15) * PER)));
            }
        }
        __syncthreads();
    }

    // Unresolved tiles past the stop point contribute nothing
    if (tid < NWORD && tid > sStopT) alive[tid] = 0ull;
    __syncthreads();

    // ---------- Phase 5: ranks + emit top-K with NEG padding ----------
    if (tid == 0) {
        int acc = 0;
        #pragma unroll
        for (int w = 0; w < NWORD; w++) { wp[w] = acc; acc += __popcll(alive[w]); }
        wp[NWORD] = acc;
    }
    __syncthreads();
    const int T = wp[NWORD];
    float* o = out + ((size_t)(b * 2 + c)) * Kq * 3;

    const u64 aw = alive[tid >> 4];
    #pragma unroll
    for (int r = 0; r < PER; r++) {
        int p = base + r;
        int bit = p & 63;
        u64 lowmask = (bit == 0) ? 0ull : ((1ull << bit) - 1ull);
        int  kr   = wp[p >> 6] + __popcll(aw & lowmask);
        bool kept = (aw >> bit) & 1ull;
        if (kept) {
            if (kr < Kq) {
                o[kr * 3 + 0] = myLo[r];
                o[kr * 3 + 1] = myHi[r];
                o[kr * 3 + 2] = key_to_score((unsigned)(v[r] >> 32));
            }
        } else {
            int nr = p - kr;                       // non-kept rank (lowest pos first)
            if (T < Kq && nr < Kq - T) {
                int slot = T + nr;
                o[slot * 3 + 0] = myLo[r];
                o[slot * 3 + 1] = myHi[r];
                o[slot * 3 + 2] = NEGV;
            }
        }
    }
}

extern "C" void kernel_launch(void* const* d_in, const int* in_sizes, int n_in,
                              void* d_out, int out_size)
{
    const float* logit  = (const float*)d_in[0];   // [16,2048,3]
    const float* reg    = (const float*)d_in[1];   // [16,2048,6]
    const float* prop   = (const float*)d_in[2];   // [16,2048,2]
    const int*   ishape = (const int*)d_in[3];     // scalar
    float* out = (float*)d_out;                    // [16,2,100,3]

    roiheads_kernel<<<Bq * (Cq - 1), THREADS>>>(logit, reg, prop, ishape, out);
}